// round 11
// baseline (speedup 1.0000x reference)
#include <cuda_runtime.h>
#include <cuda_bf16.h>
#include <cuda_fp16.h>
#include <cstdint>
#include <math.h>

// Problem constants
constexpr int B = 2, S = 2048, H = 16, D = 64, E = 1024; // E = H*D
constexpr int M_TOT = B * S;                              // 4096
constexpr int EW = E / 2;                                 // 512 half2 words per row
constexpr int DW = D / 2;                                 // 32 half2 words per head row
constexpr size_t WH_MAT = (size_t)E * EW;                 // words per transposed W

// Scratch (device globals — allocation-free). uint32 = half2 packed.
__device__ uint32_t g_Xh[(size_t)M_TOT * EW];             // X fp16 [m][kw]
__device__ uint32_t g_Wh[(size_t)4 * WH_MAT];             // Wq,Wk,Wv,Wo transposed fp16 [n][kw]
__device__ uint32_t g_Qh[(size_t)B * H * S * DW];         // Q fp16 [token][dw] (pre-scaled 1/8)
__device__ uint32_t g_Kh[(size_t)B * H * S * DW];         // K fp16 [token][dw]
__device__ uint32_t g_Vh[(size_t)B * H * (S / 2) * D];    // V fp16 half2 (key-pair, dim)
__device__ uint32_t g_Yh[(size_t)M_TOT * EW];             // Y fp16 [m][kw]
__device__ float g_sin[(size_t)S * 32];

// ---------------------------------------------------------------------------
// helpers
// ---------------------------------------------------------------------------
__device__ __forceinline__ void mma_f16(float c[4],
                                        uint32_t a0, uint32_t a1, uint32_t a2, uint32_t a3,
                                        uint32_t b0, uint32_t b1) {
    asm volatile(
        "mma.sync.aligned.m16n8k16.row.col.f32.f16.f16.f32 "
        "{%0,%1,%2,%3},{%4,%5,%6,%7},{%8,%9},{%0,%1,%2,%3};"
        : "+f"(c[0]), "+f"(c[1]), "+f"(c[2]), "+f"(c[3])
        : "r"(a0), "r"(a1), "r"(a2), "r"(a3), "r"(b0), "r"(b1));
}

__device__ __forceinline__ void ldsm_x4(uint32_t& r0, uint32_t& r1,
                                        uint32_t& r2, uint32_t& r3, uint32_t addr) {
    asm volatile("ldmatrix.sync.aligned.m8n8.x4.shared.b16 {%0,%1,%2,%3}, [%4];"
        : "=r"(r0), "=r"(r1), "=r"(r2), "=r"(r3) : "r"(addr));
}

__device__ __forceinline__ uint32_t pack_h2(float lo, float hi) {
    __half2 h = __floats2half2_rn(lo, hi);
    return *reinterpret_cast<uint32_t*>(&h);
}

__device__ __forceinline__ void cp16(uint32_t dst, const uint32_t* src) {
    asm volatile("cp.async.cg.shared.global [%0], [%1], 16;" :: "r"(dst), "l"(src));
}

// ---------------------------------------------------------------------------
// RoPE sin table (reference's c = sin bug replicated)
// ---------------------------------------------------------------------------
__global__ void sin_kernel() {
    int i = blockIdx.x * 256 + threadIdx.x;
    if (i < S * 32) {
        int s = i >> 5, j = i & 31;
        float theta = exp2f(-(float)j * (13.287712379549449f / 16.0f));
        g_sin[i] = sinf((float)s * theta);
    }
}

// ---------------------------------------------------------------------------
// X -> fp16 packed [m][kw]
// ---------------------------------------------------------------------------
__global__ __launch_bounds__(256) void cvt_x_kernel(const float* __restrict__ x)
{
    size_t i8 = ((size_t)blockIdx.x * 256 + threadIdx.x) * 8;
    float4 v0 = *(const float4*)&x[i8];
    float4 v1 = *(const float4*)&x[i8 + 4];
    uint4 o = make_uint4(pack_h2(v0.x, v0.y), pack_h2(v0.z, v0.w),
                         pack_h2(v1.x, v1.y), pack_h2(v1.z, v1.w));
    *(uint4*)&g_Xh[i8 / 2] = o;
}

// ---------------------------------------------------------------------------
// W -> transposed fp16 [n][kw] via smem tile (64x64)
// ---------------------------------------------------------------------------
__global__ __launch_bounds__(256) void transpose_w_kernel(
    const float* __restrict__ Wq, const float* __restrict__ Wk,
    const float* __restrict__ Wv, const float* __restrict__ Wo)
{
    __shared__ float ts[64][68];
    const int mat = blockIdx.z;
    const float* W = (mat == 0) ? Wq : (mat == 1) ? Wk : (mat == 2) ? Wv : Wo;
    const int k0 = blockIdx.x * 64, n0 = blockIdx.y * 64;
    const int tid = threadIdx.x;

    #pragma unroll
    for (int i = 0; i < 4; i++) {
        int f = tid + i * 256;
        int r = f >> 4, cq = (f & 15) * 4;
        float4 v = *(const float4*)&W[(size_t)(k0 + r) * E + n0 + cq];
        ts[r][cq] = v.x; ts[r][cq + 1] = v.y; ts[r][cq + 2] = v.z; ts[r][cq + 3] = v.w;
    }
    __syncthreads();

    int c = tid >> 2, wq = (tid & 3) * 8;
    uint32_t* dst = g_Wh + mat * WH_MAT + (size_t)(n0 + c) * EW + k0 / 2 + wq;
    #pragma unroll
    for (int w = 0; w < 8; w++)
        dst[w] = pack_h2(ts[2 * (wq + w)][c], ts[2 * (wq + w) + 1][c]);
}

// ---------------------------------------------------------------------------
// fp16 cp.async 4-stage GEMM mainloop, ldmatrix fragment loads.
// A: [m][kw], Bt: [n][kw]. Stage = 32 dims (16 words). Pitch 20 -> LDSM
// phases tile all 32 banks (20r mod 32 distinct windows).
// ---------------------------------------------------------------------------
constexpr int GP = 20;                    // smem pitch (words)
constexpr int HSTG_W = 2 * 128 * GP;      // words per stage (A+B) = 5120
constexpr int GEMM_SMEM = 4 * HSTG_W * 4; // 81920 B

__device__ __forceinline__ void gemm_issue(const uint32_t* Ah, const uint32_t* Bt,
                                           int row0, int col0, int kw0,
                                           uint32_t abase, int tid)
{
    uint32_t bbase = abase + 128 * GP * 4;
    #pragma unroll
    for (int i = 0; i < 2; i++) {
        int f = tid + i * 256;
        int r = f >> 2, qw = (f & 3) * 4;
        cp16(abase + (uint32_t)(r * GP + qw) * 4,
             Ah + (size_t)(row0 + r) * EW + kw0 + qw);
        cp16(bbase + (uint32_t)(r * GP + qw) * 4,
             Bt + (size_t)(col0 + r) * EW + kw0 + qw);
    }
}

__device__ __forceinline__ void gemm_mma(uint32_t abase, uint32_t bbase,
                                         float (&acc)[4][4][4],
                                         const uint32_t (&aoff)[4],
                                         const uint32_t (&boff)[2])
{
    #pragma unroll
    for (int s = 0; s < 2; s++) {
        uint32_t af[4][4], bf[4][2];
        #pragma unroll
        for (int im = 0; im < 4; im++)
            ldsm_x4(af[im][0], af[im][1], af[im][2], af[im][3],
                    abase + (aoff[im] + 8 * s) * 4);
        #pragma unroll
        for (int ip = 0; ip < 2; ip++)
            ldsm_x4(bf[2 * ip][0], bf[2 * ip][1], bf[2 * ip + 1][0], bf[2 * ip + 1][1],
                    bbase + (boff[ip] + 8 * s) * 4);
        #pragma unroll
        for (int im = 0; im < 4; im++)
            #pragma unroll
            for (int in = 0; in < 4; in++)
                mma_f16(acc[im][in], af[im][0], af[im][1], af[im][2], af[im][3],
                        bf[in][0], bf[in][1]);
    }
}

__device__ __forceinline__ void gemm128(const uint32_t* __restrict__ Ah,
                                        const uint32_t* __restrict__ Bt,
                                        int row0, int col0,
                                        uint32_t* sm, float (&acc)[4][4][4], int tid)
{
    const int lane = tid & 31, warp = tid >> 5;
    const int wm = warp >> 2, wn = warp & 3;

    // ldmatrix lane offsets (words)
    uint32_t aoff[4], boff[2];
    #pragma unroll
    for (int im = 0; im < 4; im++)
        aoff[im] = (wm * 64 + im * 16 + (lane & 15)) * GP + ((lane >> 4) << 2);
    #pragma unroll
    for (int ip = 0; ip < 2; ip++)
        boff[ip] = (wn * 32 + ip * 16 + (lane & 7) + ((lane & 16) >> 1)) * GP
                   + ((lane & 8) >> 1);

    uint32_t smbase = (uint32_t)__cvta_generic_to_shared(sm);

    #pragma unroll
    for (int p = 0; p < 3; p++) {
        gemm_issue(Ah, Bt, row0, col0, p * 16, smbase + (uint32_t)(p * HSTG_W) * 4, tid);
        asm volatile("cp.async.commit_group;" ::: "memory");
    }

    const int NS = EW / 16; // 32 stages
    for (int s = 0; s < NS; s++) {
        asm volatile("cp.async.wait_group 2;" ::: "memory");
        __syncthreads();
        if (s + 3 < NS) {
            int st = (s + 3) & 3;
            gemm_issue(Ah, Bt, row0, col0, (s + 3) * 16,
                       smbase + (uint32_t)(st * HSTG_W) * 4, tid);
        }
        asm volatile("cp.async.commit_group;" ::: "memory");
        int cur = s & 3;
        gemm_mma(smbase + (uint32_t)(cur * HSTG_W) * 4,
                 smbase + (uint32_t)(cur * HSTG_W + 128 * GP) * 4,
                 acc, aoff, boff);
    }
}

// ---------------------------------------------------------------------------
// QKV projection + fused RoPE epilogue (layouts unchanged from R10)
// ---------------------------------------------------------------------------
constexpr int QKV_SMEM = GEMM_SMEM;

__global__ __launch_bounds__(256) void qkv_kernel()
{
    extern __shared__ uint32_t sm[];
    const int which = blockIdx.z;

    const int tid = threadIdx.x;
    const int row0 = blockIdx.y * 128;
    const int col0 = blockIdx.x * 128;

    float acc[4][4][4] = {};
    gemm128(g_Xh, g_Wh + which * WH_MAT, row0, col0, sm, acc, tid);
    __syncthreads();

    float* Cs = (float*)sm; // [128][132]
    {
        const int lane = tid & 31, warp = tid >> 5;
        const int wm = warp >> 2, wn = warp & 3;
        const int gid = lane >> 2, tig = lane & 3;
        #pragma unroll
        for (int im = 0; im < 4; im++)
            #pragma unroll
            for (int in = 0; in < 4; in++) {
                int r = wm * 64 + im * 16 + gid;
                int c = wn * 32 + in * 8 + 2 * tig;
                Cs[r * 132 + c]           = acc[im][in][0];
                Cs[r * 132 + c + 1]       = acc[im][in][1];
                Cs[(r + 8) * 132 + c]     = acc[im][in][2];
                Cs[(r + 8) * 132 + c + 1] = acc[im][in][3];
            }
    }
    __syncthreads();

    const int h0 = col0 >> 6;
    if (which < 2) {
        uint32_t* out = (which == 0) ? g_Qh : g_Kh;
        const float qs = (which == 0) ? 0.125f : 1.0f;
        #pragma unroll 4
        for (int it = 0; it < 32; it++) {
            int e = tid + it * 256;
            int r = e >> 6, cw = e & 63;
            int c = 2 * cw;
            int grow = row0 + r;
            int b = grow >> 11, s = grow & 2047;
            int h = h0 + (c >> 6), d = c & 63;
            float sn0 = g_sin[(s << 5) + (d & 31)];
            float sn1 = g_sin[(s << 5) + ((d + 1) & 31)];
            float v0 = Cs[r * 132 + c],       p0 = Cs[r * 132 + (c ^ 32)];
            float v1 = Cs[r * 132 + c + 1],   p1 = Cs[r * 132 + ((c + 1) ^ 32)];
            float val0 = (d < 32) ? sn0 * (v0 - p0) : sn0 * (v0 + p0);
            float val1 = (d < 32) ? sn1 * (v1 - p1) : sn1 * (v1 + p1);
            out[(size_t)(((b * H + h) * S) + s) * DW + (d >> 1)] =
                pack_h2(val0 * qs, val1 * qs);
        }
    } else {
        #pragma unroll 4
        for (int it = 0; it < 32; it++) {
            int e = tid + it * 256;
            int rp = e >> 7, c = e & 127;
            int grow = row0 + 2 * rp;
            int b = grow >> 11, s = grow & 2047;
            int h = h0 + (c >> 6), d = c & 63;
            uint32_t pk = pack_h2(Cs[(2 * rp) * 132 + c], Cs[(2 * rp + 1) * 132 + c]);
            g_Vh[(((b * H + h) * (S / 2)) + (s >> 1)) * D + d] = pk;
        }
    }
}

// ---------------------------------------------------------------------------
// Output projection
// ---------------------------------------------------------------------------
__global__ __launch_bounds__(256) void out_proj_kernel(
    const float* __restrict__ bo, float* __restrict__ out)
{
    extern __shared__ uint32_t sm[];
    const int tid = threadIdx.x;
    const int row0 = blockIdx.y * 128;
    const int col0 = blockIdx.x * 128;

    float acc[4][4][4] = {};
    gemm128(g_Yh, g_Wh + 3 * WH_MAT, row0, col0, sm, acc, tid);

    const int lane = tid & 31, warp = tid >> 5;
    const int wm = warp >> 2, wn = warp & 3;
    const int gid = lane >> 2, tig = lane & 3;

    #pragma unroll
    for (int im = 0; im < 4; im++)
        #pragma unroll
        for (int in = 0; in < 4; in++) {
            int r = row0 + wm * 64 + im * 16 + gid;
            int c = col0 + wn * 32 + in * 8 + 2 * tig;
            float b0 = bo[c], b1 = bo[c + 1];
            float2 v0 = make_float2(acc[im][in][0] + b0, acc[im][in][1] + b1);
            float2 v1 = make_float2(acc[im][in][2] + b0, acc[im][in][3] + b1);
            *(float2*)&out[(size_t)r * E + c]       = v0;
            *(float2*)&out[(size_t)(r + 8) * E + c] = v1;
        }
}

// ---------------------------------------------------------------------------
// Flash attention, fp16 mma, ldmatrix for Q/K fragments.
// ---------------------------------------------------------------------------
constexpr int QKP = 36;              // pitch Qs/Ks (4r mod 32 -> conflict-free LDSM)
constexpr int VP = 72;               // pitch Vs
constexpr int KSTG = 64 * QKP;
constexpr int VSTG = 32 * VP;
constexpr int ATTN_SMEM = (128 * QKP + 2 * KSTG + 2 * VSTG) * 4; // 55296 B

__global__ __launch_bounds__(256, 2) void attn_kernel()
{
    extern __shared__ uint32_t sm[];
    uint32_t* Qs = sm;                     // [128][QKP]
    uint32_t* Ks = Qs + 128 * QKP;         // [2][64][QKP]
    uint32_t* Vs = Ks + 2 * KSTG;          // [2][32][VP]

    const int qt = (gridDim.x - 1) - blockIdx.x; // heavy tiles first
    const int h = blockIdx.y, b = blockIdx.z;
    const int tid = threadIdx.x;
    const int w = tid >> 5, lane = tid & 31;
    const int gid = lane >> 2, tig = lane & 3;
    const int qkbase = ((b * H + h) * S) * DW;
    const int vbase = ((b * H + h) * (S / 2)) * D;
    const int q0 = qt * 128;

    const uint32_t qsb = (uint32_t)__cvta_generic_to_shared(Qs);
    const uint32_t ksb = (uint32_t)__cvta_generic_to_shared(Ks);
    const uint32_t vsb = (uint32_t)__cvta_generic_to_shared(Vs);

    // ldmatrix lane offsets (words)
    const uint32_t qoff = (w * 16 + (lane & 15)) * QKP + ((lane >> 4) << 2);
    uint32_t koff[4];
    #pragma unroll
    for (int ip = 0; ip < 4; ip++)
        koff[ip] = (ip * 16 + (lane & 7) + ((lane & 16) >> 1)) * QKP + ((lane & 8) >> 1);

    auto issue_kv = [&](int k0, int buf) {
        #pragma unroll
        for (int i = 0; i < 2; i++) {
            int f = tid + i * 256;
            int j = f >> 3, qw = (f & 7) * 4;
            cp16(ksb + (uint32_t)(buf * KSTG + j * QKP + qw) * 4,
                 g_Kh + qkbase + (k0 + j) * DW + qw);
        }
        #pragma unroll
        for (int i = 0; i < 2; i++) {
            int f = tid + i * 256;
            int jp = f >> 4, dq = (f & 15) * 4;
            cp16(vsb + (uint32_t)(buf * VSTG + jp * VP + dq) * 4,
                 g_Vh + vbase + ((k0 >> 1) + jp) * D + dq);
        }
        asm volatile("cp.async.commit_group;" ::: "memory");
    };

    issue_kv(0, 0);
    #pragma unroll
    for (int it = 0; it < 4; it++) {
        int f = tid + it * 256;
        int row = f >> 3, qw = (f & 7) * 4;
        uint4 v = *(const uint4*)&g_Qh[qkbase + (q0 + row) * DW + qw];
        *(uint4*)&Qs[row * QKP + qw] = v;
    }

    const int r0 = w * 16 + gid;
    const int grow0 = q0 + r0;

    float m0 = -1e30f, m1 = -1e30f, l0 = 0.0f, l1 = 0.0f;
    float o[8][4] = {};

    const int NKT = 2 * qt + 2;
    for (int kt = 0; kt < NKT; kt++) {
        const int cur = kt & 1, nxt = cur ^ 1;
        __syncthreads();
        if (kt + 1 < NKT) issue_kv((kt + 1) * 64, nxt);
        else asm volatile("cp.async.commit_group;" ::: "memory");
        asm volatile("cp.async.wait_group 1;" ::: "memory");
        __syncthreads();

        const uint32_t kcb = ksb + (uint32_t)(cur * KSTG) * 4;
        const uint32_t* Vc = Vs + cur * VSTG;
        const int k0 = kt * 64;

        // S = Q @ K^T (fp16, ldmatrix fragments)
        float sacc[8][4] = {};
        #pragma unroll
        for (int kk = 0; kk < 4; kk++) {
            uint32_t a0, a1, a2, a3;
            ldsm_x4(a0, a1, a2, a3, qsb + (qoff + 8 * kk) * 4);
            #pragma unroll
            for (int ip = 0; ip < 4; ip++) {
                uint32_t b00, b01, b10, b11;
                ldsm_x4(b00, b01, b10, b11, kcb + (koff[ip] + 8 * kk) * 4);
                mma_f16(sacc[2 * ip],     a0, a1, a2, a3, b00, b01);
                mma_f16(sacc[2 * ip + 1], a0, a1, a2, a3, b10, b11);
            }
        }

        // Causal mask (only the last two k-tiles cross the diagonal)
        if (kt >= 2 * qt) {
            #pragma unroll
            for (int in = 0; in < 8; in++) {
                int gc = k0 + in * 8 + 2 * tig;
                if (gc     > grow0)     sacc[in][0] = -1e30f;
                if (gc + 1 > grow0)     sacc[in][1] = -1e30f;
                if (gc     > grow0 + 8) sacc[in][2] = -1e30f;
                if (gc + 1 > grow0 + 8) sacc[in][3] = -1e30f;
            }
        }

        // Online softmax (rows r0, r0+8; reduce over the 4 tig lanes)
        float mx0 = -1e30f, mx1 = -1e30f;
        #pragma unroll
        for (int in = 0; in < 8; in++) {
            mx0 = fmaxf(mx0, fmaxf(sacc[in][0], sacc[in][1]));
            mx1 = fmaxf(mx1, fmaxf(sacc[in][2], sacc[in][3]));
        }
        mx0 = fmaxf(mx0, __shfl_xor_sync(0xFFFFFFFFu, mx0, 1));
        mx0 = fmaxf(mx0, __shfl_xor_sync(0xFFFFFFFFu, mx0, 2));
        mx1 = fmaxf(mx1, __shfl_xor_sync(0xFFFFFFFFu, mx1, 1));
        mx1 = fmaxf(mx1, __shfl_xor_sync(0xFFFFFFFFu, mx1, 2));
        float mn0 = fmaxf(m0, mx0), mn1 = fmaxf(m1, mx1);
        float cr0 = __expf(m0 - mn0), cr1 = __expf(m1 - mn1);

        float rs0 = 0.0f, rs1 = 0.0f;
        #pragma unroll
        for (int in = 0; in < 8; in++) {
            sacc[in][0] = __expf(sacc[in][0] - mn0);
            sacc[in][1] = __expf(sacc[in][1] - mn0);
            sacc[in][2] = __expf(sacc[in][2] - mn1);
            sacc[in][3] = __expf(sacc[in][3] - mn1);
            rs0 += sacc[in][0] + sacc[in][1];
            rs1 += sacc[in][2] + sacc[in][3];
        }
        rs0 += __shfl_xor_sync(0xFFFFFFFFu, rs0, 1);
        rs0 += __shfl_xor_sync(0xFFFFFFFFu, rs0, 2);
        rs1 += __shfl_xor_sync(0xFFFFFFFFu, rs1, 1);
        rs1 += __shfl_xor_sync(0xFFFFFFFFu, rs1, 2);
        l0 = l0 * cr0 + rs0;
        l1 = l1 * cr1 + rs1;
        m0 = mn0; m1 = mn1;
        #pragma unroll
        for (int in = 0; in < 8; in++) {
            o[in][0] *= cr0; o[in][1] *= cr0;
            o[in][2] *= cr1; o[in][3] *= cr1;
        }

        // O += P @ V  (fp16; P acc layout == A fragment layout)
        #pragma unroll
        for (int kk = 0; kk < 4; kk++) {
            uint32_t a0 = pack_h2(sacc[2 * kk][0],     sacc[2 * kk][1]);
            uint32_t a1 = pack_h2(sacc[2 * kk][2],     sacc[2 * kk][3]);
            uint32_t a2 = pack_h2(sacc[2 * kk + 1][0], sacc[2 * kk + 1][1]);
            uint32_t a3 = pack_h2(sacc[2 * kk + 1][2], sacc[2 * kk + 1][3]);
            int jp0 = kk * 8;
            #pragma unroll
            for (int in = 0; in < 8; in++) {
                uint32_t b0 = Vc[(jp0 + tig) * VP + in * 8 + gid];
                uint32_t b1 = Vc[(jp0 + tig + 4) * VP + in * 8 + gid];
                mma_f16(o[in], a0, a1, a2, a3, b0, b1);
            }
        }
    }

    // Epilogue: normalize, write Y as fp16 words [m][kw]
    float inv0 = 1.0f / l0, inv1 = 1.0f / l1;
    #pragma unroll
    for (int in = 0; in < 8; in++) {
        int cw = h * 32 + in * 4 + tig;
        g_Yh[(size_t)(b * S + grow0) * EW + cw]     = pack_h2(o[in][0] * inv0, o[in][1] * inv0);
        g_Yh[(size_t)(b * S + grow0 + 8) * EW + cw] = pack_h2(o[in][2] * inv1, o[in][3] * inv1);
    }
}

// ---------------------------------------------------------------------------
extern "C" void kernel_launch(void* const* d_in, const int* in_sizes, int n_in,
                              void* d_out, int out_size)
{
    (void)in_sizes; (void)n_in; (void)out_size;
    const float* x  = (const float*)d_in[0];
    const float* Wq = (const float*)d_in[1];
    const float* Wk = (const float*)d_in[2];
    const float* Wv = (const float*)d_in[3];
    const float* Wo = (const float*)d_in[4];
    const float* bo = (const float*)d_in[5];
    float* out = (float*)d_out;

    cudaFuncSetAttribute(qkv_kernel,
                         cudaFuncAttributeMaxDynamicSharedMemorySize, QKV_SMEM);
    cudaFuncSetAttribute(out_proj_kernel,
                         cudaFuncAttributeMaxDynamicSharedMemorySize, GEMM_SMEM);
    cudaFuncSetAttribute(attn_kernel,
                         cudaFuncAttributeMaxDynamicSharedMemorySize, ATTN_SMEM);

    sin_kernel<<<(S * 32 + 255) / 256, 256>>>();
    cvt_x_kernel<<<(M_TOT * E) / (256 * 8), 256>>>(x);
    dim3 gt(E / 64, E / 64, 4);
    transpose_w_kernel<<<gt, 256>>>(Wq, Wk, Wv, Wo);

    dim3 g1(E / 128, M_TOT / 128, 3);
    qkv_kernel<<<g1, 256, QKV_SMEM>>>();

    dim3 g2(S / 128, H, B);
    attn_kernel<<<g2, 256, ATTN_SMEM>>>();

    dim3 g3(E / 128, M_TOT / 128);
    out_proj_kernel<<<g3, 256, GEMM_SMEM>>>(bo, out);
}

// round 13
// speedup vs baseline: 1.5754x; 1.5754x over previous
#include <cuda_runtime.h>
#include <cuda_bf16.h>
#include <cuda_fp16.h>
#include <cstdint>
#include <math.h>

// Problem constants
constexpr int B = 2, S = 2048, H = 16, D = 64, E = 1024; // E = H*D
constexpr int M_TOT = B * S;                              // 4096
constexpr int EW = E / 2;                                 // 512 half2 words per row
constexpr int DW = D / 2;                                 // 32 half2 words per head row
constexpr size_t WH_MAT = (size_t)E * EW;                 // words per transposed W

// Scratch (device globals — allocation-free). uint32 = half2 packed.
__device__ uint32_t g_Xh[(size_t)M_TOT * EW];             // X fp16 [m][kw]
__device__ uint32_t g_Wh[(size_t)4 * WH_MAT];             // Wq,Wk,Wv,Wo transposed fp16 [n][kw]
__device__ uint32_t g_Qh[(size_t)B * H * S * DW];         // Q fp16 [token][dw] (pre-scaled 1/8)
__device__ uint32_t g_Kh[(size_t)B * H * S * DW];         // K fp16 [token][dw]
__device__ uint32_t g_Vh[(size_t)B * H * (S / 2) * D];    // V fp16 half2 (key-pair, dim)
__device__ uint32_t g_Yh[(size_t)M_TOT * EW];             // Y fp16 [m][kw]
__device__ float g_sin[(size_t)S * 32];

// ---------------------------------------------------------------------------
// helpers
// ---------------------------------------------------------------------------
__device__ __forceinline__ void mma_f16(float c[4],
                                        uint32_t a0, uint32_t a1, uint32_t a2, uint32_t a3,
                                        uint32_t b0, uint32_t b1) {
    asm volatile(
        "mma.sync.aligned.m16n8k16.row.col.f32.f16.f16.f32 "
        "{%0,%1,%2,%3},{%4,%5,%6,%7},{%8,%9},{%0,%1,%2,%3};"
        : "+f"(c[0]), "+f"(c[1]), "+f"(c[2]), "+f"(c[3])
        : "r"(a0), "r"(a1), "r"(a2), "r"(a3), "r"(b0), "r"(b1));
}

__device__ __forceinline__ uint32_t pack_h2(float lo, float hi) {
    __half2 h = __floats2half2_rn(lo, hi);
    return *reinterpret_cast<uint32_t*>(&h);
}

__device__ __forceinline__ void cp16(uint32_t dst, const uint32_t* src) {
    asm volatile("cp.async.cg.shared.global [%0], [%1], 16;" :: "r"(dst), "l"(src));
}

// ---------------------------------------------------------------------------
// RoPE sin table (reference's c = sin bug replicated)
// ---------------------------------------------------------------------------
__global__ void sin_kernel() {
    int i = blockIdx.x * 256 + threadIdx.x;
    if (i < S * 32) {
        int s = i >> 5, j = i & 31;
        float theta = exp2f(-(float)j * (13.287712379549449f / 16.0f));
        g_sin[i] = sinf((float)s * theta);
    }
}

// ---------------------------------------------------------------------------
// X -> fp16 packed [m][kw]
// ---------------------------------------------------------------------------
__global__ __launch_bounds__(256) void cvt_x_kernel(const float* __restrict__ x)
{
    size_t i8 = ((size_t)blockIdx.x * 256 + threadIdx.x) * 8;
    float4 v0 = *(const float4*)&x[i8];
    float4 v1 = *(const float4*)&x[i8 + 4];
    uint4 o = make_uint4(pack_h2(v0.x, v0.y), pack_h2(v0.z, v0.w),
                         pack_h2(v1.x, v1.y), pack_h2(v1.z, v1.w));
    *(uint4*)&g_Xh[i8 / 2] = o;
}

// ---------------------------------------------------------------------------
// W -> transposed fp16 [n][kw] via smem tile (64x64)
// ---------------------------------------------------------------------------
__global__ __launch_bounds__(256) void transpose_w_kernel(
    const float* __restrict__ Wq, const float* __restrict__ Wk,
    const float* __restrict__ Wv, const float* __restrict__ Wo)
{
    __shared__ float ts[64][68];
    const int mat = blockIdx.z;
    const float* W = (mat == 0) ? Wq : (mat == 1) ? Wk : (mat == 2) ? Wv : Wo;
    const int k0 = blockIdx.x * 64, n0 = blockIdx.y * 64;
    const int tid = threadIdx.x;

    #pragma unroll
    for (int i = 0; i < 4; i++) {
        int f = tid + i * 256;
        int r = f >> 4, cq = (f & 15) * 4;
        float4 v = *(const float4*)&W[(size_t)(k0 + r) * E + n0 + cq];
        ts[r][cq] = v.x; ts[r][cq + 1] = v.y; ts[r][cq + 2] = v.z; ts[r][cq + 3] = v.w;
    }
    __syncthreads();

    int c = tid >> 2, wq = (tid & 3) * 8;
    uint32_t* dst = g_Wh + mat * WH_MAT + (size_t)(n0 + c) * EW + k0 / 2 + wq;
    #pragma unroll
    for (int w = 0; w < 8; w++)
        dst[w] = pack_h2(ts[2 * (wq + w)][c], ts[2 * (wq + w) + 1][c]);
}

// ---------------------------------------------------------------------------
// fp16 cp.async double-buffered GEMM mainloop, 64-dim stages.
// A: [m][kw], Bt: [n][kw]. Stage = 64 dims (32 words), pitch 36 -> banks
// 4*gid+tig all distinct (conflict-free fragment LDS).
// 8 warps (2m x 4n), warp tile 64x32, m16n8k16. 2 barriers per 64-dim stage.
// ---------------------------------------------------------------------------
constexpr int GP = 36;                    // smem pitch (words)
constexpr int HSTG_W = 2 * 128 * GP;      // words per stage (A+B) = 9216
constexpr int GEMM_SMEM = 2 * HSTG_W * 4; // 73728 B

__device__ __forceinline__ void gemm_issue(const uint32_t* Ah, const uint32_t* Bt,
                                           int row0, int col0, int kw0,
                                           uint32_t abase, int tid)
{
    uint32_t bbase = abase + 128 * GP * 4;
    #pragma unroll
    for (int i = 0; i < 4; i++) {
        int f = tid + i * 256;            // 0..1023
        int r = f >> 3, qw = (f & 7) * 4; // 128 rows x 8 quads
        cp16(abase + (uint32_t)(r * GP + qw) * 4,
             Ah + (size_t)(row0 + r) * EW + kw0 + qw);
        cp16(bbase + (uint32_t)(r * GP + qw) * 4,
             Bt + (size_t)(col0 + r) * EW + kw0 + qw);
    }
    asm volatile("cp.async.commit_group;" ::: "memory");
}

__device__ __forceinline__ void gemm_mma(const uint32_t* a, const uint32_t* b,
                                         float (&acc)[4][4][4],
                                         int wm, int wn, int gid, int tig)
{
    #pragma unroll
    for (int kk = 0; kk < 4; kk++) {      // 4 k16 groups per 64-dim stage
        int w0 = 8 * kk + tig, w1 = w0 + 4;
        uint32_t af[4][4], bf[4][2];
        #pragma unroll
        for (int im = 0; im < 4; im++) {
            int mb = wm * 64 + im * 16 + gid;
            af[im][0] = a[mb * GP + w0];
            af[im][1] = a[(mb + 8) * GP + w0];
            af[im][2] = a[mb * GP + w1];
            af[im][3] = a[(mb + 8) * GP + w1];
        }
        #pragma unroll
        for (int in = 0; in < 4; in++) {
            int nb = wn * 32 + in * 8 + gid;
            bf[in][0] = b[nb * GP + w0];
            bf[in][1] = b[nb * GP + w1];
        }
        #pragma unroll
        for (int im = 0; im < 4; im++)
            #pragma unroll
            for (int in = 0; in < 4; in++)
                mma_f16(acc[im][in], af[im][0], af[im][1], af[im][2], af[im][3],
                        bf[in][0], bf[in][1]);
    }
}

__device__ __forceinline__ void gemm128(const uint32_t* __restrict__ Ah,
                                        const uint32_t* __restrict__ Bt,
                                        int row0, int col0,
                                        uint32_t* sm, float (&acc)[4][4][4], int tid)
{
    const int lane = tid & 31, warp = tid >> 5;
    const int wm = warp >> 2, wn = warp & 3;
    const int gid = lane >> 2, tig = lane & 3;

    uint32_t smbase = (uint32_t)__cvta_generic_to_shared(sm);

    gemm_issue(Ah, Bt, row0, col0, 0, smbase, tid);

    const int NS = EW / 32; // 16 stages of 32 words (64 dims)
    for (int s = 0; s < NS; s++) {
        __syncthreads(); // all warps done reading the buffer we're about to fill
        if (s + 1 < NS)
            gemm_issue(Ah, Bt, row0, col0, (s + 1) * 32,
                       smbase + (uint32_t)(((s + 1) & 1) * HSTG_W) * 4, tid);
        else
            asm volatile("cp.async.commit_group;" ::: "memory");
        asm volatile("cp.async.wait_group 1;" ::: "memory"); // stage s resident
        __syncthreads();
        int cur = s & 1;
        gemm_mma(sm + cur * HSTG_W, sm + cur * HSTG_W + 128 * GP, acc, wm, wn, gid, tig);
    }
}

// ---------------------------------------------------------------------------
// QKV projection + fused RoPE epilogue
// ---------------------------------------------------------------------------
constexpr int QKV_SMEM = GEMM_SMEM; // 73728 >= 128*132*4 = 67584

__global__ __launch_bounds__(256, 2) void qkv_kernel()
{
    extern __shared__ uint32_t sm[];
    const int which = blockIdx.z;

    const int tid = threadIdx.x;
    const int row0 = blockIdx.y * 128;
    const int col0 = blockIdx.x * 128;

    float acc[4][4][4] = {};
    gemm128(g_Xh, g_Wh + which * WH_MAT, row0, col0, sm, acc, tid);
    __syncthreads();

    float* Cs = (float*)sm; // [128][132]
    {
        const int lane = tid & 31, warp = tid >> 5;
        const int wm = warp >> 2, wn = warp & 3;
        const int gid = lane >> 2, tig = lane & 3;
        #pragma unroll
        for (int im = 0; im < 4; im++)
            #pragma unroll
            for (int in = 0; in < 4; in++) {
                int r = wm * 64 + im * 16 + gid;
                int c = wn * 32 + in * 8 + 2 * tig;
                Cs[r * 132 + c]           = acc[im][in][0];
                Cs[r * 132 + c + 1]       = acc[im][in][1];
                Cs[(r + 8) * 132 + c]     = acc[im][in][2];
                Cs[(r + 8) * 132 + c + 1] = acc[im][in][3];
            }
    }
    __syncthreads();

    const int h0 = col0 >> 6;
    if (which < 2) {
        uint32_t* out = (which == 0) ? g_Qh : g_Kh;
        const float qs = (which == 0) ? 0.125f : 1.0f;
        #pragma unroll 4
        for (int it = 0; it < 32; it++) {
            int e = tid + it * 256;
            int r = e >> 6, cw = e & 63;
            int c = 2 * cw;
            int grow = row0 + r;
            int b = grow >> 11, s = grow & 2047;
            int h = h0 + (c >> 6), d = c & 63;
            float sn0 = g_sin[(s << 5) + (d & 31)];
            float sn1 = g_sin[(s << 5) + ((d + 1) & 31)];
            float v0 = Cs[r * 132 + c],       p0 = Cs[r * 132 + (c ^ 32)];
            float v1 = Cs[r * 132 + c + 1],   p1 = Cs[r * 132 + ((c + 1) ^ 32)];
            float val0 = (d < 32) ? sn0 * (v0 - p0) : sn0 * (v0 + p0);
            float val1 = (d < 32) ? sn1 * (v1 - p1) : sn1 * (v1 + p1);
            out[(size_t)(((b * H + h) * S) + s) * DW + (d >> 1)] =
                pack_h2(val0 * qs, val1 * qs);
        }
    } else {
        #pragma unroll 4
        for (int it = 0; it < 32; it++) {
            int e = tid + it * 256;
            int rp = e >> 7, c = e & 127;
            int grow = row0 + 2 * rp;
            int b = grow >> 11, s = grow & 2047;
            int h = h0 + (c >> 6), d = c & 63;
            uint32_t pk = pack_h2(Cs[(2 * rp) * 132 + c], Cs[(2 * rp + 1) * 132 + c]);
            g_Vh[(((b * H + h) * (S / 2)) + (s >> 1)) * D + d] = pk;
        }
    }
}

// ---------------------------------------------------------------------------
// Output projection: out = Y @ Wo + bo
// ---------------------------------------------------------------------------
__global__ __launch_bounds__(256, 2) void out_proj_kernel(
    const float* __restrict__ bo, float* __restrict__ out)
{
    extern __shared__ uint32_t sm[];
    const int tid = threadIdx.x;
    const int row0 = blockIdx.y * 128;
    const int col0 = blockIdx.x * 128;

    float acc[4][4][4] = {};
    gemm128(g_Yh, g_Wh + 3 * WH_MAT, row0, col0, sm, acc, tid);

    const int lane = tid & 31, warp = tid >> 5;
    const int wm = warp >> 2, wn = warp & 3;
    const int gid = lane >> 2, tig = lane & 3;

    #pragma unroll
    for (int im = 0; im < 4; im++)
        #pragma unroll
        for (int in = 0; in < 4; in++) {
            int r = row0 + wm * 64 + im * 16 + gid;
            int c = col0 + wn * 32 + in * 8 + 2 * tig;
            float b0 = bo[c], b1 = bo[c + 1];
            float2 v0 = make_float2(acc[im][in][0] + b0, acc[im][in][1] + b1);
            float2 v1 = make_float2(acc[im][in][2] + b0, acc[im][in][3] + b1);
            *(float2*)&out[(size_t)r * E + c]       = v0;
            *(float2*)&out[(size_t)(r + 8) * E + c] = v1;
        }
}

// ---------------------------------------------------------------------------
// Flash attention (unchanged from R10): fp16 mma, cp.async double-buffered K/V,
// PV with P passed directly from accumulators.
// ---------------------------------------------------------------------------
constexpr int QKP = 36;
constexpr int VP = 72;
constexpr int KSTG = 64 * QKP;
constexpr int VSTG = 32 * VP;
constexpr int ATTN_SMEM = (128 * QKP + 2 * KSTG + 2 * VSTG) * 4; // 55296 B

__global__ __launch_bounds__(256, 2) void attn_kernel()
{
    extern __shared__ uint32_t smf[];
    uint32_t* Qs = smf;                    // [128][QKP]
    uint32_t* Ks = Qs + 128 * QKP;         // [2][64][QKP]
    uint32_t* Vs = Ks + 2 * KSTG;          // [2][32][VP]

    const int qt = (gridDim.x - 1) - blockIdx.x;
    const int h = blockIdx.y, b = blockIdx.z;
    const int tid = threadIdx.x;
    const int w = tid >> 5, lane = tid & 31;
    const int gid = lane >> 2, tig = lane & 3;
    const int qkbase = ((b * H + h) * S) * DW;
    const int vbase = ((b * H + h) * (S / 2)) * D;
    const int q0 = qt * 128;

    const uint32_t ksb = (uint32_t)__cvta_generic_to_shared(Ks);
    const uint32_t vsb = (uint32_t)__cvta_generic_to_shared(Vs);

    auto issue_kv = [&](int k0, int buf) {
        #pragma unroll
        for (int i = 0; i < 2; i++) {
            int f = tid + i * 256;
            int j = f >> 3, qw = (f & 7) * 4;
            cp16(ksb + (uint32_t)(buf * KSTG + j * QKP + qw) * 4,
                 g_Kh + qkbase + (k0 + j) * DW + qw);
        }
        #pragma unroll
        for (int i = 0; i < 2; i++) {
            int f = tid + i * 256;
            int jp = f >> 4, dq = (f & 15) * 4;
            cp16(vsb + (uint32_t)(buf * VSTG + jp * VP + dq) * 4,
                 g_Vh + vbase + ((k0 >> 1) + jp) * D + dq);
        }
        asm volatile("cp.async.commit_group;" ::: "memory");
    };

    issue_kv(0, 0);
    #pragma unroll
    for (int it = 0; it < 4; it++) {
        int f = tid + it * 256;
        int row = f >> 3, qw = (f & 7) * 4;
        uint4 v = *(const uint4*)&g_Qh[qkbase + (q0 + row) * DW + qw];
        *(uint4*)&Qs[row * QKP + qw] = v;
    }

    const int r0 = w * 16 + gid;
    const int grow0 = q0 + r0;

    float m0 = -1e30f, m1 = -1e30f, l0 = 0.0f, l1 = 0.0f;
    float o[8][4] = {};

    const int NKT = 2 * qt + 2;
    for (int kt = 0; kt < NKT; kt++) {
        const int cur = kt & 1, nxt = cur ^ 1;
        __syncthreads();
        if (kt + 1 < NKT) issue_kv((kt + 1) * 64, nxt);
        else asm volatile("cp.async.commit_group;" ::: "memory");
        asm volatile("cp.async.wait_group 1;" ::: "memory");
        __syncthreads();

        const uint32_t* Kc = Ks + cur * KSTG;
        const uint32_t* Vc = Vs + cur * VSTG;
        const int k0 = kt * 64;

        float sacc[8][4] = {};
        #pragma unroll
        for (int kk = 0; kk < 4; kk++) {
            int w0 = 8 * kk + tig, w1 = w0 + 4;
            uint32_t a0 = Qs[r0 * QKP + w0];
            uint32_t a1 = Qs[(r0 + 8) * QKP + w0];
            uint32_t a2 = Qs[r0 * QKP + w1];
            uint32_t a3 = Qs[(r0 + 8) * QKP + w1];
            #pragma unroll
            for (int in = 0; in < 8; in++) {
                uint32_t b0 = Kc[(in * 8 + gid) * QKP + w0];
                uint32_t b1 = Kc[(in * 8 + gid) * QKP + w1];
                mma_f16(sacc[in], a0, a1, a2, a3, b0, b1);
            }
        }

        if (kt >= 2 * qt) {
            #pragma unroll
            for (int in = 0; in < 8; in++) {
                int gc = k0 + in * 8 + 2 * tig;
                if (gc     > grow0)     sacc[in][0] = -1e30f;
                if (gc + 1 > grow0)     sacc[in][1] = -1e30f;
                if (gc     > grow0 + 8) sacc[in][2] = -1e30f;
                if (gc + 1 > grow0 + 8) sacc[in][3] = -1e30f;
            }
        }

        float mx0 = -1e30f, mx1 = -1e30f;
        #pragma unroll
        for (int in = 0; in < 8; in++) {
            mx0 = fmaxf(mx0, fmaxf(sacc[in][0], sacc[in][1]));
            mx1 = fmaxf(mx1, fmaxf(sacc[in][2], sacc[in][3]));
        }
        mx0 = fmaxf(mx0, __shfl_xor_sync(0xFFFFFFFFu, mx0, 1));
        mx0 = fmaxf(mx0, __shfl_xor_sync(0xFFFFFFFFu, mx0, 2));
        mx1 = fmaxf(mx1, __shfl_xor_sync(0xFFFFFFFFu, mx1, 1));
        mx1 = fmaxf(mx1, __shfl_xor_sync(0xFFFFFFFFu, mx1, 2));
        float mn0 = fmaxf(m0, mx0), mn1 = fmaxf(m1, mx1);
        float cr0 = __expf(m0 - mn0), cr1 = __expf(m1 - mn1);

        float rs0 = 0.0f, rs1 = 0.0f;
        #pragma unroll
        for (int in = 0; in < 8; in++) {
            sacc[in][0] = __expf(sacc[in][0] - mn0);
            sacc[in][1] = __expf(sacc[in][1] - mn0);
            sacc[in][2] = __expf(sacc[in][2] - mn1);
            sacc[in][3] = __expf(sacc[in][3] - mn1);
            rs0 += sacc[in][0] + sacc[in][1];
            rs1 += sacc[in][2] + sacc[in][3];
        }
        rs0 += __shfl_xor_sync(0xFFFFFFFFu, rs0, 1);
        rs0 += __shfl_xor_sync(0xFFFFFFFFu, rs0, 2);
        rs1 += __shfl_xor_sync(0xFFFFFFFFu, rs1, 1);
        rs1 += __shfl_xor_sync(0xFFFFFFFFu, rs1, 2);
        l0 = l0 * cr0 + rs0;
        l1 = l1 * cr1 + rs1;
        m0 = mn0; m1 = mn1;
        #pragma unroll
        for (int in = 0; in < 8; in++) {
            o[in][0] *= cr0; o[in][1] *= cr0;
            o[in][2] *= cr1; o[in][3] *= cr1;
        }

        #pragma unroll
        for (int kk = 0; kk < 4; kk++) {
            uint32_t a0 = pack_h2(sacc[2 * kk][0],     sacc[2 * kk][1]);
            uint32_t a1 = pack_h2(sacc[2 * kk][2],     sacc[2 * kk][3]);
            uint32_t a2 = pack_h2(sacc[2 * kk + 1][0], sacc[2 * kk + 1][1]);
            uint32_t a3 = pack_h2(sacc[2 * kk + 1][2], sacc[2 * kk + 1][3]);
            int jp0 = kk * 8;
            #pragma unroll
            for (int in = 0; in < 8; in++) {
                uint32_t b0 = Vc[(jp0 + tig) * VP + in * 8 + gid];
                uint32_t b1 = Vc[(jp0 + tig + 4) * VP + in * 8 + gid];
                mma_f16(o[in], a0, a1, a2, a3, b0, b1);
            }
        }
    }

    float inv0 = 1.0f / l0, inv1 = 1.0f / l1;
    #pragma unroll
    for (int in = 0; in < 8; in++) {
        int cw = h * 32 + in * 4 + tig;
        g_Yh[(size_t)(b * S + grow0) * EW + cw]     = pack_h2(o[in][0] * inv0, o[in][1] * inv0);
        g_Yh[(size_t)(b * S + grow0 + 8) * EW + cw] = pack_h2(o[in][2] * inv1, o[in][3] * inv1);
    }
}

// ---------------------------------------------------------------------------
extern "C" void kernel_launch(void* const* d_in, const int* in_sizes, int n_in,
                              void* d_out, int out_size)
{
    (void)in_sizes; (void)n_in; (void)out_size;
    const float* x  = (const float*)d_in[0];
    const float* Wq = (const float*)d_in[1];
    const float* Wk = (const float*)d_in[2];
    const float* Wv = (const float*)d_in[3];
    const float* Wo = (const float*)d_in[4];
    const float* bo = (const float*)d_in[5];
    float* out = (float*)d_out;

    cudaFuncSetAttribute(qkv_kernel,
                         cudaFuncAttributeMaxDynamicSharedMemorySize, QKV_SMEM);
    cudaFuncSetAttribute(out_proj_kernel,
                         cudaFuncAttributeMaxDynamicSharedMemorySize, GEMM_SMEM);
    cudaFuncSetAttribute(attn_kernel,
                         cudaFuncAttributeMaxDynamicSharedMemorySize, ATTN_SMEM);

    sin_kernel<<<(S * 32 + 255) / 256, 256>>>();
    cvt_x_kernel<<<(M_TOT * E) / (256 * 8), 256>>>(x);
    dim3 gt(E / 64, E / 64, 4);
    transpose_w_kernel<<<gt, 256>>>(Wq, Wk, Wv, Wo);

    dim3 g1(E / 128, M_TOT / 128, 3);
    qkv_kernel<<<g1, 256, QKV_SMEM>>>();

    dim3 g2(S / 128, H, B);
    attn_kernel<<<g2, 256, ATTN_SMEM>>>();

    dim3 g3(E / 128, M_TOT / 128);
    out_proj_kernel<<<g3, 256, GEMM_SMEM>>>(bo, out);
}

// round 14
// speedup vs baseline: 1.5884x; 1.0083x over previous
#include <cuda_runtime.h>
#include <cuda_bf16.h>
#include <cuda_fp16.h>
#include <cstdint>
#include <math.h>

// Problem constants
constexpr int B = 2, S = 2048, H = 16, D = 64, E = 1024; // E = H*D
constexpr int M_TOT = B * S;                              // 4096
constexpr int EW = E / 2;                                 // 512 half2 words per row
constexpr int DW = D / 2;                                 // 32 half2 words per head row
constexpr size_t WH_MAT = (size_t)E * EW;                 // words per transposed W

// Scratch (device globals — allocation-free). uint32 = half2 packed.
__device__ uint32_t g_Xh[(size_t)M_TOT * EW];             // X fp16 [m][kw]
__device__ uint32_t g_Wh[(size_t)4 * WH_MAT];             // Wq,Wk,Wv,Wo transposed fp16 [n][kw]
__device__ uint32_t g_Qh[(size_t)B * H * S * DW];         // Q fp16 [token][dw] (pre-scaled 1/8)
__device__ uint32_t g_Kh[(size_t)B * H * S * DW];         // K fp16 [token][dw]
__device__ uint32_t g_Vh[(size_t)B * H * (S / 2) * D];    // V fp16 half2 (key-pair, dim)
__device__ uint32_t g_Yh[(size_t)M_TOT * EW];             // Y fp16 [m][kw]
__device__ float g_sin[(size_t)S * 32];

// ---------------------------------------------------------------------------
// helpers
// ---------------------------------------------------------------------------
__device__ __forceinline__ void mma_f16(float c[4],
                                        uint32_t a0, uint32_t a1, uint32_t a2, uint32_t a3,
                                        uint32_t b0, uint32_t b1) {
    asm volatile(
        "mma.sync.aligned.m16n8k16.row.col.f32.f16.f16.f32 "
        "{%0,%1,%2,%3},{%4,%5,%6,%7},{%8,%9},{%0,%1,%2,%3};"
        : "+f"(c[0]), "+f"(c[1]), "+f"(c[2]), "+f"(c[3])
        : "r"(a0), "r"(a1), "r"(a2), "r"(a3), "r"(b0), "r"(b1));
}

__device__ __forceinline__ uint32_t pack_h2(float lo, float hi) {
    __half2 h = __floats2half2_rn(lo, hi);
    return *reinterpret_cast<uint32_t*>(&h);
}

__device__ __forceinline__ void cp16(uint32_t dst, const uint32_t* src) {
    asm volatile("cp.async.cg.shared.global [%0], [%1], 16;" :: "r"(dst), "l"(src));
}

// ---------------------------------------------------------------------------
// Prep: sin table + X->fp16 + W transposes, one launch.
// blocks [0,2048): cvt_x; [2048,3072): transpose; [3072,3328): sin
// ---------------------------------------------------------------------------
__global__ __launch_bounds__(256) void prep_kernel(
    const float* __restrict__ x,
    const float* __restrict__ Wq, const float* __restrict__ Wk,
    const float* __restrict__ Wv, const float* __restrict__ Wo)
{
    __shared__ float ts[64][68];
    const int bx = blockIdx.x;
    const int tid = threadIdx.x;

    if (bx < 2048) {
        size_t i8 = ((size_t)bx * 256 + tid) * 8;
        float4 v0 = *(const float4*)&x[i8];
        float4 v1 = *(const float4*)&x[i8 + 4];
        uint4 o = make_uint4(pack_h2(v0.x, v0.y), pack_h2(v0.z, v0.w),
                             pack_h2(v1.x, v1.y), pack_h2(v1.z, v1.w));
        *(uint4*)&g_Xh[i8 / 2] = o;
    } else if (bx < 3072) {
        const int id = bx - 2048;
        const int mat = id >> 8, sub = id & 255;
        const int k0 = (sub & 15) * 64, n0 = (sub >> 4) * 64;
        const float* W = (mat == 0) ? Wq : (mat == 1) ? Wk : (mat == 2) ? Wv : Wo;

        #pragma unroll
        for (int i = 0; i < 4; i++) {
            int f = tid + i * 256;
            int r = f >> 4, cq = (f & 15) * 4;
            float4 v = *(const float4*)&W[(size_t)(k0 + r) * E + n0 + cq];
            ts[r][cq] = v.x; ts[r][cq + 1] = v.y; ts[r][cq + 2] = v.z; ts[r][cq + 3] = v.w;
        }
        __syncthreads();

        int c = tid >> 2, wq = (tid & 3) * 8;
        uint32_t* dst = g_Wh + mat * WH_MAT + (size_t)(n0 + c) * EW + k0 / 2 + wq;
        #pragma unroll
        for (int w = 0; w < 8; w++)
            dst[w] = pack_h2(ts[2 * (wq + w)][c], ts[2 * (wq + w) + 1][c]);
    } else {
        int i = (bx - 3072) * 256 + tid;
        int s = i >> 5, j = i & 31;
        float theta = exp2f(-(float)j * (13.287712379549449f / 16.0f));
        g_sin[i] = sinf((float)s * theta);
    }
}

// ---------------------------------------------------------------------------
// fp16 cp.async double-buffered GEMM, 64-dim stages, register-double-buffered
// fragments. A: [m][kw], Bt: [n][kw]. Pitch 36 -> conflict-free LDS.
// ---------------------------------------------------------------------------
constexpr int GP = 36;                    // smem pitch (words)
constexpr int HSTG_W = 2 * 128 * GP;      // words per stage (A+B) = 9216
constexpr int GEMM_SMEM = 2 * HSTG_W * 4; // 73728 B

__device__ __forceinline__ void gemm_issue(const uint32_t* Ah, const uint32_t* Bt,
                                           int row0, int col0, int kw0,
                                           uint32_t abase, int tid)
{
    uint32_t bbase = abase + 128 * GP * 4;
    #pragma unroll
    for (int i = 0; i < 4; i++) {
        int f = tid + i * 256;
        int r = f >> 3, qw = (f & 7) * 4;
        cp16(abase + (uint32_t)(r * GP + qw) * 4,
             Ah + (size_t)(row0 + r) * EW + kw0 + qw);
        cp16(bbase + (uint32_t)(r * GP + qw) * 4,
             Bt + (size_t)(col0 + r) * EW + kw0 + qw);
    }
    asm volatile("cp.async.commit_group;" ::: "memory");
}

__device__ __forceinline__ void ldfrag(const uint32_t* a, const uint32_t* b,
                                       int kk, int wm, int wn, int gid, int tig,
                                       uint32_t (&af)[4][4], uint32_t (&bf)[4][2])
{
    int w0 = 8 * kk + tig, w1 = w0 + 4;
    #pragma unroll
    for (int im = 0; im < 4; im++) {
        int mb = wm * 64 + im * 16 + gid;
        af[im][0] = a[mb * GP + w0];
        af[im][1] = a[(mb + 8) * GP + w0];
        af[im][2] = a[mb * GP + w1];
        af[im][3] = a[(mb + 8) * GP + w1];
    }
    #pragma unroll
    for (int in = 0; in < 4; in++) {
        int nb = wn * 32 + in * 8 + gid;
        bf[in][0] = b[nb * GP + w0];
        bf[in][1] = b[nb * GP + w1];
    }
}

__device__ __forceinline__ void gemm_mma(const uint32_t* a, const uint32_t* b,
                                         float (&acc)[4][4][4],
                                         int wm, int wn, int gid, int tig)
{
    uint32_t af[2][4][4], bf[2][4][2];
    ldfrag(a, b, 0, wm, wn, gid, tig, af[0], bf[0]);
    #pragma unroll
    for (int kk = 0; kk < 4; kk++) {
        int c = kk & 1;
        if (kk < 3)
            ldfrag(a, b, kk + 1, wm, wn, gid, tig, af[c ^ 1], bf[c ^ 1]);
        #pragma unroll
        for (int im = 0; im < 4; im++)
            #pragma unroll
            for (int in = 0; in < 4; in++)
                mma_f16(acc[im][in], af[c][im][0], af[c][im][1], af[c][im][2],
                        af[c][im][3], bf[c][in][0], bf[c][in][1]);
    }
}

__device__ __forceinline__ void gemm128(const uint32_t* __restrict__ Ah,
                                        const uint32_t* __restrict__ Bt,
                                        int row0, int col0,
                                        uint32_t* sm, float (&acc)[4][4][4], int tid)
{
    const int lane = tid & 31, warp = tid >> 5;
    const int wm = warp >> 2, wn = warp & 3;
    const int gid = lane >> 2, tig = lane & 3;

    uint32_t smbase = (uint32_t)__cvta_generic_to_shared(sm);

    gemm_issue(Ah, Bt, row0, col0, 0, smbase, tid);

    const int NS = EW / 32; // 16 stages of 64 dims
    for (int s = 0; s < NS; s++) {
        __syncthreads();
        if (s + 1 < NS)
            gemm_issue(Ah, Bt, row0, col0, (s + 1) * 32,
                       smbase + (uint32_t)(((s + 1) & 1) * HSTG_W) * 4, tid);
        else
            asm volatile("cp.async.commit_group;" ::: "memory");
        asm volatile("cp.async.wait_group 1;" ::: "memory");
        __syncthreads();
        int cur = s & 1;
        gemm_mma(sm + cur * HSTG_W, sm + cur * HSTG_W + 128 * GP, acc, wm, wn, gid, tig);
    }
}

// ---------------------------------------------------------------------------
// QKV projection + fused RoPE epilogue
// ---------------------------------------------------------------------------
constexpr int QKV_SMEM = GEMM_SMEM; // 73728 >= 128*132*4 = 67584

__global__ __launch_bounds__(256, 2) void qkv_kernel()
{
    extern __shared__ uint32_t sm[];
    const int which = blockIdx.z;

    const int tid = threadIdx.x;
    const int row0 = blockIdx.y * 128;
    const int col0 = blockIdx.x * 128;

    float acc[4][4][4] = {};
    gemm128(g_Xh, g_Wh + which * WH_MAT, row0, col0, sm, acc, tid);
    __syncthreads();

    float* Cs = (float*)sm; // [128][132]
    {
        const int lane = tid & 31, warp = tid >> 5;
        const int wm = warp >> 2, wn = warp & 3;
        const int gid = lane >> 2, tig = lane & 3;
        #pragma unroll
        for (int im = 0; im < 4; im++)
            #pragma unroll
            for (int in = 0; in < 4; in++) {
                int r = wm * 64 + im * 16 + gid;
                int c = wn * 32 + in * 8 + 2 * tig;
                Cs[r * 132 + c]           = acc[im][in][0];
                Cs[r * 132 + c + 1]       = acc[im][in][1];
                Cs[(r + 8) * 132 + c]     = acc[im][in][2];
                Cs[(r + 8) * 132 + c + 1] = acc[im][in][3];
            }
    }
    __syncthreads();

    const int h0 = col0 >> 6;
    if (which < 2) {
        uint32_t* out = (which == 0) ? g_Qh : g_Kh;
        const float qs = (which == 0) ? 0.125f : 1.0f;
        #pragma unroll 4
        for (int it = 0; it < 32; it++) {
            int e = tid + it * 256;
            int r = e >> 6, cw = e & 63;
            int c = 2 * cw;
            int grow = row0 + r;
            int b = grow >> 11, s = grow & 2047;
            int h = h0 + (c >> 6), d = c & 63;
            float sn0 = g_sin[(s << 5) + (d & 31)];
            float sn1 = g_sin[(s << 5) + ((d + 1) & 31)];
            float v0 = Cs[r * 132 + c],       p0 = Cs[r * 132 + (c ^ 32)];
            float v1 = Cs[r * 132 + c + 1],   p1 = Cs[r * 132 + ((c + 1) ^ 32)];
            float val0 = (d < 32) ? sn0 * (v0 - p0) : sn0 * (v0 + p0);
            float val1 = (d < 32) ? sn1 * (v1 - p1) : sn1 * (v1 + p1);
            out[(size_t)(((b * H + h) * S) + s) * DW + (d >> 1)] =
                pack_h2(val0 * qs, val1 * qs);
        }
    } else {
        #pragma unroll 4
        for (int it = 0; it < 32; it++) {
            int e = tid + it * 256;
            int rp = e >> 7, c = e & 127;
            int grow = row0 + 2 * rp;
            int b = grow >> 11, s = grow & 2047;
            int h = h0 + (c >> 6), d = c & 63;
            uint32_t pk = pack_h2(Cs[(2 * rp) * 132 + c], Cs[(2 * rp + 1) * 132 + c]);
            g_Vh[(((b * H + h) * (S / 2)) + (s >> 1)) * D + d] = pk;
        }
    }
}

// ---------------------------------------------------------------------------
// Output projection: out = Y @ Wo + bo
// ---------------------------------------------------------------------------
__global__ __launch_bounds__(256, 2) void out_proj_kernel(
    const float* __restrict__ bo, float* __restrict__ out)
{
    extern __shared__ uint32_t sm[];
    const int tid = threadIdx.x;
    const int row0 = blockIdx.y * 128;
    const int col0 = blockIdx.x * 128;

    float acc[4][4][4] = {};
    gemm128(g_Yh, g_Wh + 3 * WH_MAT, row0, col0, sm, acc, tid);

    const int lane = tid & 31, warp = tid >> 5;
    const int wm = warp >> 2, wn = warp & 3;
    const int gid = lane >> 2, tig = lane & 3;

    #pragma unroll
    for (int im = 0; im < 4; im++)
        #pragma unroll
        for (int in = 0; in < 4; in++) {
            int r = row0 + wm * 64 + im * 16 + gid;
            int c = col0 + wn * 32 + in * 8 + 2 * tig;
            float b0 = bo[c], b1 = bo[c + 1];
            float2 v0 = make_float2(acc[im][in][0] + b0, acc[im][in][1] + b1);
            float2 v1 = make_float2(acc[im][in][2] + b0, acc[im][in][3] + b1);
            *(float2*)&out[(size_t)r * E + c]       = v0;
            *(float2*)&out[(size_t)(r + 8) * E + c] = v1;
        }
}

// ---------------------------------------------------------------------------
// Flash attention: fp16 mma, 128-key load tiles (two 64-key compute halves),
// cp.async double-buffered, PV with P passed directly from accumulators.
// ---------------------------------------------------------------------------
constexpr int QKP = 36;
constexpr int VP = 72;
constexpr int KSTG = 128 * QKP;      // 4608 words
constexpr int VSTG = 64 * VP;        // 4608 words
constexpr int ATTN_SMEM = (128 * QKP + 2 * KSTG + 2 * VSTG) * 4; // 92160 B

__global__ __launch_bounds__(256, 2) void attn_kernel()
{
    extern __shared__ uint32_t smf[];
    uint32_t* Qs = smf;                    // [128][QKP]
    uint32_t* Ks = Qs + 128 * QKP;         // [2][128][QKP]
    uint32_t* Vs = Ks + 2 * KSTG;          // [2][64][VP]

    const int qt = (gridDim.x - 1) - blockIdx.x; // heavy tiles first
    const int h = blockIdx.y, b = blockIdx.z;
    const int tid = threadIdx.x;
    const int w = tid >> 5, lane = tid & 31;
    const int gid = lane >> 2, tig = lane & 3;
    const int qkbase = ((b * H + h) * S) * DW;
    const int vbase = ((b * H + h) * (S / 2)) * D;
    const int q0 = qt * 128;

    const uint32_t ksb = (uint32_t)__cvta_generic_to_shared(Ks);
    const uint32_t vsb = (uint32_t)__cvta_generic_to_shared(Vs);

    // one 128-key tile per issue
    auto issue_kv = [&](int k0, int buf) {
        #pragma unroll
        for (int i = 0; i < 4; i++) {
            int f = tid + i * 256;
            int j = f >> 3, qw = (f & 7) * 4;      // 128 rows x 8 quads
            cp16(ksb + (uint32_t)(buf * KSTG + j * QKP + qw) * 4,
                 g_Kh + qkbase + (k0 + j) * DW + qw);
        }
        #pragma unroll
        for (int i = 0; i < 4; i++) {
            int f = tid + i * 256;
            int jp = f >> 4, dq = (f & 15) * 4;    // 64 pair-rows x 16 quads
            cp16(vsb + (uint32_t)(buf * VSTG + jp * VP + dq) * 4,
                 g_Vh + vbase + ((k0 >> 1) + jp) * D + dq);
        }
        asm volatile("cp.async.commit_group;" ::: "memory");
    };

    issue_kv(0, 0);
    #pragma unroll
    for (int it = 0; it < 4; it++) {
        int f = tid + it * 256;
        int row = f >> 3, qw = (f & 7) * 4;
        uint4 v = *(const uint4*)&g_Qh[qkbase + (q0 + row) * DW + qw];
        *(uint4*)&Qs[row * QKP + qw] = v;
    }

    const int r0 = w * 16 + gid;
    const int grow0 = q0 + r0;

    float m0 = -1e30f, m1 = -1e30f, l0 = 0.0f, l1 = 0.0f;
    float o[8][4] = {};

    const int NKT = qt + 1;
    for (int kt = 0; kt < NKT; kt++) {
        const int cur = kt & 1;
        __syncthreads();
        if (kt + 1 < NKT) issue_kv((kt + 1) * 128, cur ^ 1);
        else asm volatile("cp.async.commit_group;" ::: "memory");
        asm volatile("cp.async.wait_group 1;" ::: "memory");
        __syncthreads();

        const bool diag = (kt == NKT - 1);

        #pragma unroll
        for (int half = 0; half < 2; half++) {
            const uint32_t* Kc = Ks + cur * KSTG + half * 64 * QKP;
            const uint32_t* Vc = Vs + cur * VSTG + half * 32 * VP;
            const int k0 = kt * 128 + half * 64;

            // S = Q @ K^T (fp16 inputs, fp32 accum)
            float sacc[8][4] = {};
            #pragma unroll
            for (int kk = 0; kk < 4; kk++) {
                int w0 = 8 * kk + tig, w1 = w0 + 4;
                uint32_t a0 = Qs[r0 * QKP + w0];
                uint32_t a1 = Qs[(r0 + 8) * QKP + w0];
                uint32_t a2 = Qs[r0 * QKP + w1];
                uint32_t a3 = Qs[(r0 + 8) * QKP + w1];
                #pragma unroll
                for (int in = 0; in < 8; in++) {
                    uint32_t b0 = Kc[(in * 8 + gid) * QKP + w0];
                    uint32_t b1 = Kc[(in * 8 + gid) * QKP + w1];
                    mma_f16(sacc[in], a0, a1, a2, a3, b0, b1);
                }
            }

            if (diag) {
                #pragma unroll
                for (int in = 0; in < 8; in++) {
                    int gc = k0 + in * 8 + 2 * tig;
                    if (gc     > grow0)     sacc[in][0] = -1e30f;
                    if (gc + 1 > grow0)     sacc[in][1] = -1e30f;
                    if (gc     > grow0 + 8) sacc[in][2] = -1e30f;
                    if (gc + 1 > grow0 + 8) sacc[in][3] = -1e30f;
                }
            }

            // Online softmax (rows r0, r0+8; reduce over the 4 tig lanes)
            float mx0 = -1e30f, mx1 = -1e30f;
            #pragma unroll
            for (int in = 0; in < 8; in++) {
                mx0 = fmaxf(mx0, fmaxf(sacc[in][0], sacc[in][1]));
                mx1 = fmaxf(mx1, fmaxf(sacc[in][2], sacc[in][3]));
            }
            mx0 = fmaxf(mx0, __shfl_xor_sync(0xFFFFFFFFu, mx0, 1));
            mx0 = fmaxf(mx0, __shfl_xor_sync(0xFFFFFFFFu, mx0, 2));
            mx1 = fmaxf(mx1, __shfl_xor_sync(0xFFFFFFFFu, mx1, 1));
            mx1 = fmaxf(mx1, __shfl_xor_sync(0xFFFFFFFFu, mx1, 2));
            float mn0 = fmaxf(m0, mx0), mn1 = fmaxf(m1, mx1);
            float cr0 = __expf(m0 - mn0), cr1 = __expf(m1 - mn1);

            float rs0 = 0.0f, rs1 = 0.0f;
            #pragma unroll
            for (int in = 0; in < 8; in++) {
                sacc[in][0] = __expf(sacc[in][0] - mn0);
                sacc[in][1] = __expf(sacc[in][1] - mn0);
                sacc[in][2] = __expf(sacc[in][2] - mn1);
                sacc[in][3] = __expf(sacc[in][3] - mn1);
                rs0 += sacc[in][0] + sacc[in][1];
                rs1 += sacc[in][2] + sacc[in][3];
            }
            rs0 += __shfl_xor_sync(0xFFFFFFFFu, rs0, 1);
            rs0 += __shfl_xor_sync(0xFFFFFFFFu, rs0, 2);
            rs1 += __shfl_xor_sync(0xFFFFFFFFu, rs1, 1);
            rs1 += __shfl_xor_sync(0xFFFFFFFFu, rs1, 2);
            l0 = l0 * cr0 + rs0;
            l1 = l1 * cr1 + rs1;
            m0 = mn0; m1 = mn1;
            #pragma unroll
            for (int in = 0; in < 8; in++) {
                o[in][0] *= cr0; o[in][1] *= cr0;
                o[in][2] *= cr1; o[in][3] *= cr1;
            }

            // O += P @ V  (fp16; P acc layout == A fragment layout)
            #pragma unroll
            for (int kk = 0; kk < 4; kk++) {
                uint32_t a0 = pack_h2(sacc[2 * kk][0],     sacc[2 * kk][1]);
                uint32_t a1 = pack_h2(sacc[2 * kk][2],     sacc[2 * kk][3]);
                uint32_t a2 = pack_h2(sacc[2 * kk + 1][0], sacc[2 * kk + 1][1]);
                uint32_t a3 = pack_h2(sacc[2 * kk + 1][2], sacc[2 * kk + 1][3]);
                int jp0 = kk * 8;
                #pragma unroll
                for (int in = 0; in < 8; in++) {
                    uint32_t b0 = Vc[(jp0 + tig) * VP + in * 8 + gid];
                    uint32_t b1 = Vc[(jp0 + tig + 4) * VP + in * 8 + gid];
                    mma_f16(o[in], a0, a1, a2, a3, b0, b1);
                }
            }
        }
    }

    // Epilogue: normalize, write Y as fp16 words [m][kw]
    float inv0 = 1.0f / l0, inv1 = 1.0f / l1;
    #pragma unroll
    for (int in = 0; in < 8; in++) {
        int cw = h * 32 + in * 4 + tig;
        g_Yh[(size_t)(b * S + grow0) * EW + cw]     = pack_h2(o[in][0] * inv0, o[in][1] * inv0);
        g_Yh[(size_t)(b * S + grow0 + 8) * EW + cw] = pack_h2(o[in][2] * inv1, o[in][3] * inv1);
    }
}

// ---------------------------------------------------------------------------
extern "C" void kernel_launch(void* const* d_in, const int* in_sizes, int n_in,
                              void* d_out, int out_size)
{
    (void)in_sizes; (void)n_in; (void)out_size;
    const float* x  = (const float*)d_in[0];
    const float* Wq = (const float*)d_in[1];
    const float* Wk = (const float*)d_in[2];
    const float* Wv = (const float*)d_in[3];
    const float* Wo = (const float*)d_in[4];
    const float* bo = (const float*)d_in[5];
    float* out = (float*)d_out;

    cudaFuncSetAttribute(qkv_kernel,
                         cudaFuncAttributeMaxDynamicSharedMemorySize, QKV_SMEM);
    cudaFuncSetAttribute(out_proj_kernel,
                         cudaFuncAttributeMaxDynamicSharedMemorySize, GEMM_SMEM);
    cudaFuncSetAttribute(attn_kernel,
                         cudaFuncAttributeMaxDynamicSharedMemorySize, ATTN_SMEM);

    prep_kernel<<<3328, 256>>>(x, Wq, Wk, Wv, Wo);

    dim3 g1(E / 128, M_TOT / 128, 3);
    qkv_kernel<<<g1, 256, QKV_SMEM>>>();

    dim3 g2(S / 128, H, B);
    attn_kernel<<<g2, 256, ATTN_SMEM>>>();

    dim3 g3(E / 128, M_TOT / 128);
    out_proj_kernel<<<g3, 256, GEMM_SMEM>>>(bo, out);
}